// round 1
// baseline (speedup 1.0000x reference)
#include <cuda_runtime.h>
#include <math.h>

#define B_   4
#define T_   4096
#define C_   1024
#define H_   16
#define CS_  128
#define D_   64
#define NC_  32
#define EPS_ 1e-5f

// ---------------- scratch (device globals; no allocations allowed) ----------------
__device__ float g_pm  [(size_t)16384 * 1024];   // pm, then gm in-place (64 MB)
__device__ float g_lcm [(size_t)262144 * 64];    // per-chunk cumsum, [blk,s,d] (64 MB)
__device__ float g_csum[2048 * 64];              // chunk sums [bh*NC+ch, d]
__device__ float g_ncar[2048 * 64];              // normalized carries
__device__ float g_comb[(size_t)262144 * 128];   // [x_h | cards] rows (128 MB)
__device__ float g_h   [(size_t)262144 * 128];   // gelu(comb@W1) (128 MB)
__device__ float g_obuf[(size_t)16384 * 1024];   // ho scattered to (b,t,c) (64 MB)
__device__ float g_pbuf[(size_t)16384 * 1024];   // proj output pre-LN (64 MB)

__device__ __forceinline__ float warpSum(float v) {
#pragma unroll
    for (int o = 16; o > 0; o >>= 1) v += __shfl_xor_sync(0xffffffffu, v, o);
    return v;
}

// ---------------- generic tiled SGEMM with fused epilogues ----------------
// EPI: 0 = bias              (C = acc + bias[n])
//      1 = sigmoid*inplace   (C = sigmoid(acc+bias[n]) * C_old)  [gm over pm]
//      2 = gelu              (C = gelu_exact(acc+bias[n]))
//      3 = bias + scatter to (b,t,c) layout (for ho -> obuf)
template <int BM, int BN, int BK, int TM, int TN, int EPI>
__global__ __launch_bounds__((BM / TM) * (BN / TN))
void sgemm(int M, int N, int K,
           const float* __restrict__ A,
           const float* __restrict__ B,
           const float* __restrict__ bias,
           float* __restrict__ C)
{
    constexpr int NT = (BM / TM) * (BN / TN);   // 256
    __shared__ float As[BK][BM];
    __shared__ float Bs[BK][BN];

    const int tid  = threadIdx.x;
    const int crow = blockIdx.y * BM;
    const int ccol = blockIdx.x * BN;

    const float* Ab = A + (size_t)crow * K;
    const float* Bb = B + ccol;

    const int aRow = tid / (BK / 4);
    const int aCol = (tid % (BK / 4)) * 4;
    constexpr int aRowStride = NT / (BK / 4);
    const int bRow = tid / (BN / 4);
    const int bCol = (tid % (BN / 4)) * 4;
    constexpr int bRowStride = NT / (BN / 4);

    const int tRow = (tid / (BN / TN)) * TM;
    const int tCol = (tid % (BN / TN)) * TN;

    float acc[TM][TN] = {};
    float regM[TM], regN[TN];

    for (int k0 = 0; k0 < K; k0 += BK) {
#pragma unroll
        for (int r = 0; r < BM; r += aRowStride) {
            float4 v = *reinterpret_cast<const float4*>(
                &Ab[(size_t)(aRow + r) * K + k0 + aCol]);
            As[aCol + 0][aRow + r] = v.x;
            As[aCol + 1][aRow + r] = v.y;
            As[aCol + 2][aRow + r] = v.z;
            As[aCol + 3][aRow + r] = v.w;
        }
#pragma unroll
        for (int r = 0; r < BK; r += bRowStride) {
            *reinterpret_cast<float4*>(&Bs[bRow + r][bCol]) =
                *reinterpret_cast<const float4*>(&Bb[(size_t)(k0 + bRow + r) * N + bCol]);
        }
        __syncthreads();
#pragma unroll
        for (int k = 0; k < BK; k++) {
#pragma unroll
            for (int i = 0; i < TM; i++) regM[i] = As[k][tRow + i];
#pragma unroll
            for (int j = 0; j < TN; j++) regN[j] = Bs[k][tCol + j];
#pragma unroll
            for (int i = 0; i < TM; i++)
#pragma unroll
                for (int j = 0; j < TN; j++)
                    acc[i][j] += regM[i] * regN[j];
        }
        __syncthreads();
    }

#pragma unroll
    for (int i = 0; i < TM; i++) {
        const int m = crow + tRow + i;
#pragma unroll
        for (int j = 0; j < TN; j++) {
            const int n = ccol + tCol + j;
            float v = acc[i][j] + bias[n];
            if (EPI == 1) {
                const size_t idx = (size_t)m * N + n;
                const float old = C[idx];
                C[idx] = old / (1.f + __expf(-v));
            } else if (EPI == 2) {
                v = 0.5f * v * (1.f + erff(v * 0.70710678118654752440f));
                C[(size_t)m * N + n] = v;
            } else if (EPI == 3) {
                const int s = m & 127, ch = (m >> 7) & 31, h = (m >> 12) & 15, b = m >> 16;
                const size_t oidx = (((size_t)b * T_) + ch * CS_ + s) * C_ + h * D_ + n;
                C[oidx] = v;
            } else {
                C[(size_t)m * N + n] = v;
            }
        }
    }
}

// ---------------- per-chunk cumsum + chunk sums ----------------
__global__ void chunk_scan_kernel(const float* __restrict__ gm,
                                  float* __restrict__ lcm,
                                  float* __restrict__ csum)
{
    const int blk = blockIdx.x;        // (b*H + h)*NC + chunk
    const int d   = threadIdx.x;       // 64
    const int ch  = blk % NC_;
    const int h   = (blk / NC_) % H_;
    const int b   = blk / (NC_ * H_);
    const float* src = gm + (((size_t)b * T_) + ch * CS_) * C_ + h * D_ + d;
    float* dst = lcm + (size_t)blk * CS_ * D_ + d;
    float acc = 0.f;
    for (int s = 0; s < CS_; s++) {
        acc += src[(size_t)s * C_];
        dst[(size_t)s * D_] = acc;
    }
    csum[(size_t)blk * D_ + d] = acc;
}

// ---------------- cross-chunk exclusive scan + carry LayerNorm ----------------
__global__ void carry_ln_kernel(const float* __restrict__ csum,
                                const float* __restrict__ g,
                                const float* __restrict__ bb,
                                float* __restrict__ ncar)
{
    const int bh = blockIdx.x;     // b*H + h
    const int d  = threadIdx.x;    // 64
    const int lane = d & 31, w = d >> 5;
    __shared__ float sh[2];
    const float gd = g[d], bd = bb[d];
    float run = 0.f;
    for (int ch = 0; ch < NC_; ch++) {
        const float carry = run;                    // exclusive prefix
        run += csum[(size_t)(bh * NC_ + ch) * D_ + d];
        float s = warpSum(carry);
        if (lane == 0) sh[w] = s;
        __syncthreads();
        const float mean = (sh[0] + sh[1]) * (1.f / 64.f);
        __syncthreads();
        const float df = carry - mean;
        float s2 = warpSum(df * df);
        if (lane == 0) sh[w] = s2;
        __syncthreads();
        const float var = (sh[0] + sh[1]) * (1.f / 64.f);
        __syncthreads();
        ncar[(size_t)(bh * NC_ + ch) * D_ + d] = df * rsqrtf(var + EPS_) * gd + bd;
    }
}

// ---------------- cards (LN over D) + comb = [x_h | cards] ----------------
__global__ __launch_bounds__(128)
void cards_comb_kernel(const float* __restrict__ x,
                       const float* __restrict__ lcm,
                       const float* __restrict__ ncar,
                       const float* __restrict__ cg,
                       const float* __restrict__ cb,
                       float* __restrict__ comb)
{
    const int blk = blockIdx.x;      // (b*H+h)*NC + chunk
    const int s   = threadIdx.x;     // 128
    const int ch  = blk % NC_;
    const int h   = (blk / NC_) % H_;
    const int b   = blk / (NC_ * H_);

    __shared__ float ncs[D_], gs[D_], bs[D_];
    if (s < D_) { ncs[s] = ncar[(size_t)blk * D_ + s]; gs[s] = cg[s]; bs[s] = cb[s]; }
    __syncthreads();

    float v[D_];
    if (s == 0) {
#pragma unroll
        for (int d = 0; d < D_; d++) v[d] = ncs[d];
    } else {
        const float4* l4 = reinterpret_cast<const float4*>(
            lcm + ((size_t)blk * CS_ + (s - 1)) * D_);
#pragma unroll
        for (int i = 0; i < D_ / 4; i++) {
            const float4 t = l4[i];
            v[4 * i + 0] = t.x + ncs[4 * i + 0];
            v[4 * i + 1] = t.y + ncs[4 * i + 1];
            v[4 * i + 2] = t.z + ncs[4 * i + 2];
            v[4 * i + 3] = t.w + ncs[4 * i + 3];
        }
    }
    float sum = 0.f;
#pragma unroll
    for (int d = 0; d < D_; d++) sum += v[d];
    const float mean = sum * (1.f / 64.f);
    float sq = 0.f;
#pragma unroll
    for (int d = 0; d < D_; d++) { const float df = v[d] - mean; sq += df * df; }
    const float rs = rsqrtf(sq * (1.f / 64.f) + EPS_);

    const size_t row = (size_t)blk * CS_ + s;
    float4* cout = reinterpret_cast<float4*>(comb + row * 128);
    const float4* xr = reinterpret_cast<const float4*>(
        x + (((size_t)b * T_) + ch * CS_ + s) * C_ + h * D_);
#pragma unroll
    for (int i = 0; i < D_ / 4; i++) cout[i] = xr[i];
#pragma unroll
    for (int i = 0; i < D_ / 4; i++) {
        float4 t;
        t.x = (v[4 * i + 0] - mean) * rs * gs[4 * i + 0] + bs[4 * i + 0];
        t.y = (v[4 * i + 1] - mean) * rs * gs[4 * i + 1] + bs[4 * i + 1];
        t.z = (v[4 * i + 2] - mean) * rs * gs[4 * i + 2] + bs[4 * i + 2];
        t.w = (v[4 * i + 3] - mean) * rs * gs[4 * i + 3] + bs[4 * i + 3];
        cout[16 + i] = t;
    }
}

// ---------------- final LayerNorm over C + residual ----------------
__global__ __launch_bounds__(256)
void ln_res_kernel(const float* __restrict__ p, const float* __restrict__ x,
                   const float* __restrict__ g, const float* __restrict__ bb,
                   float* __restrict__ out)
{
    const int row = blockIdx.x;
    const int t   = threadIdx.x;   // 256 threads x 4 floats
    const float4 lv = reinterpret_cast<const float4*>(p + (size_t)row * C_)[t];
    float s = lv.x + lv.y + lv.z + lv.w;
    __shared__ float red[8];
    s = warpSum(s);
    if ((t & 31) == 0) red[t >> 5] = s;
    __syncthreads();
    float tot = 0.f;
#pragma unroll
    for (int i = 0; i < 8; i++) tot += red[i];
    const float mean = tot * (1.f / 1024.f);
    __syncthreads();
    const float d0 = lv.x - mean, d1 = lv.y - mean, d2 = lv.z - mean, d3 = lv.w - mean;
    float sq = d0 * d0 + d1 * d1 + d2 * d2 + d3 * d3;
    sq = warpSum(sq);
    if ((t & 31) == 0) red[t >> 5] = sq;
    __syncthreads();
    float v2 = 0.f;
#pragma unroll
    for (int i = 0; i < 8; i++) v2 += red[i];
    const float rs = rsqrtf(v2 * (1.f / 1024.f) + EPS_);
    const float4 xv = reinterpret_cast<const float4*>(x + (size_t)row * C_)[t];
    const float4 gv = reinterpret_cast<const float4*>(g)[t];
    const float4 bv = reinterpret_cast<const float4*>(bb)[t];
    float4 o;
    o.x = xv.x + d0 * rs * gv.x + bv.x;
    o.y = xv.y + d1 * rs * gv.y + bv.y;
    o.z = xv.z + d2 * rs * gv.z + bv.z;
    o.w = xv.w + d3 * rs * gv.w + bv.w;
    reinterpret_cast<float4*>(out + (size_t)row * C_)[t] = o;
}

// ---------------- launch ----------------
extern "C" void kernel_launch(void* const* d_in, const int* in_sizes, int n_in,
                              void* d_out, int out_size)
{
    const float* x       = (const float*)d_in[0];
    const float* mark_W  = (const float*)d_in[1];
    const float* mark_b  = (const float*)d_in[2];
    const float* gate_W  = (const float*)d_in[3];
    const float* gate_b  = (const float*)d_in[4];
    const float* carry_g = (const float*)d_in[5];
    const float* carry_b = (const float*)d_in[6];
    const float* card_g  = (const float*)d_in[7];
    const float* card_b  = (const float*)d_in[8];
    const float* ho1_W   = (const float*)d_in[9];
    const float* ho1_b   = (const float*)d_in[10];
    const float* ho2_W   = (const float*)d_in[11];
    const float* ho2_b   = (const float*)d_in[12];
    const float* proj_W  = (const float*)d_in[13];
    const float* proj_b  = (const float*)d_in[14];
    const float* ln_g    = (const float*)d_in[15];
    const float* ln_b    = (const float*)d_in[16];
    float* out = (float*)d_out;

    static float *pm = nullptr, *lcm, *csum, *ncar, *comb, *hbuf, *obuf, *pbuf;
    if (!pm) {
        cudaGetSymbolAddress((void**)&pm,   g_pm);
        cudaGetSymbolAddress((void**)&lcm,  g_lcm);
        cudaGetSymbolAddress((void**)&csum, g_csum);
        cudaGetSymbolAddress((void**)&ncar, g_ncar);
        cudaGetSymbolAddress((void**)&comb, g_comb);
        cudaGetSymbolAddress((void**)&hbuf, g_h);
        cudaGetSymbolAddress((void**)&obuf, g_obuf);
        cudaGetSymbolAddress((void**)&pbuf, g_pbuf);
    }

    const int M  = B_ * T_;          // 16384
    const int MR = B_ * H_ * NC_ * CS_;  // 262144

    // pm = x @ mark_W + mark_b
    sgemm<128, 128, 16, 8, 8, 0><<<dim3(C_ / 128, M / 128), 256>>>(
        M, C_, C_, x, mark_W, mark_b, pm);
    // gm = sigmoid(x @ gate_W + gate_b) * pm   (in place over pm)
    sgemm<128, 128, 16, 8, 8, 1><<<dim3(C_ / 128, M / 128), 256>>>(
        M, C_, C_, x, gate_W, gate_b, pm);
    // per-chunk cumsum + chunk sums
    chunk_scan_kernel<<<B_ * H_ * NC_, 64>>>(pm, lcm, csum);
    // exclusive cross-chunk scan + LN(carries)
    carry_ln_kernel<<<B_ * H_, 64>>>(csum, carry_g, carry_b, ncar);
    // cards LN + comb assembly
    cards_comb_kernel<<<B_ * H_ * NC_, 128>>>(x, lcm, ncar, card_g, card_b, comb);
    // h = gelu(comb @ ho1_W + ho1_b)
    sgemm<128, 128, 16, 8, 8, 2><<<dim3(1, MR / 128), 256>>>(
        MR, 128, 128, comb, ho1_W, ho1_b, hbuf);
    // ho = h @ ho2_W + ho2_b  -> scattered to (b,t,c)
    sgemm<128, 64, 16, 8, 4, 3><<<dim3(1, MR / 128), 256>>>(
        MR, 64, 128, hbuf, ho2_W, ho2_b, obuf);
    // proj
    sgemm<128, 128, 16, 8, 8, 0><<<dim3(C_ / 128, M / 128), 256>>>(
        M, C_, C_, obuf, proj_W, proj_b, pbuf);
    // final LN + residual
    ln_res_kernel<<<M, 256>>>(pbuf, x, ln_g, ln_b, out);
}

// round 2
// speedup vs baseline: 2.2103x; 2.2103x over previous
#include <cuda_runtime.h>
#include <math.h>
#include <stdint.h>

#define B_   4
#define T_   4096
#define C_   1024
#define H_   16
#define CS_  128
#define D_   64
#define NC_  32
#define EPS_ 1e-5f

// ---------------- scratch (device globals; no allocations allowed) ----------------
__device__ float g_pm  [(size_t)16384 * 1024];   // pm, then gm in-place (64 MB)
__device__ float g_lcm [(size_t)262144 * 64];    // per-chunk cumsum, [blk,s,d] (64 MB)
__device__ float g_csum[2048 * 64];              // chunk sums
__device__ float g_ncar[2048 * 64];              // normalized carries
__device__ float g_comb[(size_t)262144 * 128];   // [x_h | cards] rows (128 MB)
__device__ float g_h   [(size_t)262144 * 128];   // gelu(comb@W1) (128 MB)
__device__ float g_obuf[(size_t)16384 * 1024];   // ho scattered to (b,t,c) (64 MB)
__device__ float g_pbuf[(size_t)16384 * 1024];   // proj output pre-LN (64 MB)

__device__ __forceinline__ float warpSum(float v) {
#pragma unroll
    for (int o = 16; o > 0; o >>= 1) v += __shfl_xor_sync(0xffffffffu, v, o);
    return v;
}

__device__ __forceinline__ float tf32r(float f) {
    uint32_t u;
    asm("cvt.rna.tf32.f32 %0, %1;" : "=r"(u) : "f"(f));
    return __uint_as_float(u);
}

__device__ __forceinline__ void mma_tf32(float c[4],
                                         uint32_t a0, uint32_t a1, uint32_t a2, uint32_t a3,
                                         uint32_t b0, uint32_t b1) {
    asm volatile(
        "mma.sync.aligned.m16n8k8.row.col.f32.tf32.tf32.f32 "
        "{%0,%1,%2,%3}, {%4,%5,%6,%7}, {%8,%9}, {%0,%1,%2,%3};"
        : "+f"(c[0]), "+f"(c[1]), "+f"(c[2]), "+f"(c[3])
        : "r"(a0), "r"(a1), "r"(a2), "r"(a3), "r"(b0), "r"(b1));
}

// ---------------- TF32 tensor-core GEMM with fused epilogues ----------------
// A[M,K] row-major fp32, B[K,N] row-major fp32; inputs rounded to tf32 at staging.
// EPI: 0 = bias; 1 = sigmoid*inplace (gm over pm); 2 = gelu; 3 = bias + (b,t,c) scatter.
template <int BN, int EPI>
__global__ __launch_bounds__(256)
void tgemm(int M, int N, int K,
           const float* __restrict__ A,
           const float* __restrict__ B,
           const float* __restrict__ bias,
           float* __restrict__ C)
{
    constexpr int BM = 128, BK = 16;
    constexpr int WN  = BN / 2;        // warp tile: 32 x WN
    constexpr int NT2 = WN / 8;        // n-tiles per warp
    constexpr int BLDN  = BN / 4;      // threads per B row (float4)
    constexpr int BROWS = 256 / BLDN;  // B rows per pass
    constexpr int BITER = BK / BROWS;  // B staging passes

    __shared__ float As[2][BK][BM + 4];
    __shared__ float Bs[2][BK][BN + 4];

    const int tid  = threadIdx.x;
    const int lane = tid & 31, warp = tid >> 5;
    const int wm = (warp >> 1) * 32;
    const int wn = (warp & 1) * WN;
    const int gid = lane >> 2, tig = lane & 3;

    const int crow = blockIdx.y * BM;
    const int ccol = blockIdx.x * BN;

    // staging maps
    const int aRow = tid >> 2;                 // 0..63
    const int aCol = (tid & 3) * 4;            // 0..12
    const int bRow = tid / BLDN;
    const int bCol = (tid % BLDN) * 4;

    const float* Ab = A + (size_t)crow * K;
    const float* Bb = B + ccol;

    float acc[2][NT2][4];
#pragma unroll
    for (int i = 0; i < 2; i++)
#pragma unroll
        for (int j = 0; j < NT2; j++)
#pragma unroll
            for (int q = 0; q < 4; q++) acc[i][j][q] = 0.f;

    const int nT = K / BK;
    float4 pa[2], pb[BITER];

    // preload tile 0
#pragma unroll
    for (int r = 0; r < 2; r++)
        pa[r] = *reinterpret_cast<const float4*>(&Ab[(size_t)(aRow + r * 64) * K + aCol]);
#pragma unroll
    for (int r = 0; r < BITER; r++)
        pb[r] = *reinterpret_cast<const float4*>(&Bb[(size_t)(bRow + r * BROWS) * N + bCol]);

    int p = 0;
    // store tile 0 (with tf32 rounding)
#pragma unroll
    for (int r = 0; r < 2; r++) {
        As[0][aCol + 0][aRow + r * 64] = tf32r(pa[r].x);
        As[0][aCol + 1][aRow + r * 64] = tf32r(pa[r].y);
        As[0][aCol + 2][aRow + r * 64] = tf32r(pa[r].z);
        As[0][aCol + 3][aRow + r * 64] = tf32r(pa[r].w);
    }
#pragma unroll
    for (int r = 0; r < BITER; r++) {
        Bs[0][bRow + r * BROWS][bCol + 0] = tf32r(pb[r].x);
        Bs[0][bRow + r * BROWS][bCol + 1] = tf32r(pb[r].y);
        Bs[0][bRow + r * BROWS][bCol + 2] = tf32r(pb[r].z);
        Bs[0][bRow + r * BROWS][bCol + 3] = tf32r(pb[r].w);
    }
    __syncthreads();

    for (int t = 0; t < nT; t++) {
        const bool more = (t + 1) < nT;
        if (more) {
            const int k0 = (t + 1) * BK;
#pragma unroll
            for (int r = 0; r < 2; r++)
                pa[r] = *reinterpret_cast<const float4*>(&Ab[(size_t)(aRow + r * 64) * K + k0 + aCol]);
#pragma unroll
            for (int r = 0; r < BITER; r++)
                pb[r] = *reinterpret_cast<const float4*>(&Bb[(size_t)(k0 + bRow + r * BROWS) * N + bCol]);
        }

        // compute current tile: two k8 steps
#pragma unroll
        for (int kk = 0; kk < BK; kk += 8) {
            uint32_t af[2][4];
#pragma unroll
            for (int mt = 0; mt < 2; mt++) {
                const int m0 = wm + mt * 16;
                af[mt][0] = __float_as_uint(As[p][kk + tig    ][m0 + gid    ]);
                af[mt][1] = __float_as_uint(As[p][kk + tig    ][m0 + gid + 8]);
                af[mt][2] = __float_as_uint(As[p][kk + tig + 4][m0 + gid    ]);
                af[mt][3] = __float_as_uint(As[p][kk + tig + 4][m0 + gid + 8]);
            }
            uint32_t bf[NT2][2];
#pragma unroll
            for (int nt = 0; nt < NT2; nt++) {
                const int n0 = wn + nt * 8;
                bf[nt][0] = __float_as_uint(Bs[p][kk + tig    ][n0 + gid]);
                bf[nt][1] = __float_as_uint(Bs[p][kk + tig + 4][n0 + gid]);
            }
#pragma unroll
            for (int mt = 0; mt < 2; mt++)
#pragma unroll
                for (int nt = 0; nt < NT2; nt++)
                    mma_tf32(acc[mt][nt], af[mt][0], af[mt][1], af[mt][2], af[mt][3],
                             bf[nt][0], bf[nt][1]);
        }

        if (more) {
            const int q = p ^ 1;
#pragma unroll
            for (int r = 0; r < 2; r++) {
                As[q][aCol + 0][aRow + r * 64] = tf32r(pa[r].x);
                As[q][aCol + 1][aRow + r * 64] = tf32r(pa[r].y);
                As[q][aCol + 2][aRow + r * 64] = tf32r(pa[r].z);
                As[q][aCol + 3][aRow + r * 64] = tf32r(pa[r].w);
            }
#pragma unroll
            for (int r = 0; r < BITER; r++) {
                Bs[q][bRow + r * BROWS][bCol + 0] = tf32r(pb[r].x);
                Bs[q][bRow + r * BROWS][bCol + 1] = tf32r(pb[r].y);
                Bs[q][bRow + r * BROWS][bCol + 2] = tf32r(pb[r].z);
                Bs[q][bRow + r * BROWS][bCol + 3] = tf32r(pb[r].w);
            }
        }
        __syncthreads();
        p ^= 1;
    }

    // epilogue
#pragma unroll
    for (int mt = 0; mt < 2; mt++) {
#pragma unroll
        for (int nt = 0; nt < NT2; nt++) {
#pragma unroll
            for (int q = 0; q < 4; q++) {
                const int m = crow + wm + mt * 16 + gid + (q >> 1) * 8;
                const int n = ccol + wn + nt * 8 + tig * 2 + (q & 1);
                float v = acc[mt][nt][q] + bias[n];
                if (EPI == 1) {
                    const size_t idx = (size_t)m * N + n;
                    const float old = C[idx];
                    C[idx] = old / (1.f + __expf(-v));
                } else if (EPI == 2) {
                    v = 0.5f * v * (1.f + erff(v * 0.70710678118654752440f));
                    C[(size_t)m * N + n] = v;
                } else if (EPI == 3) {
                    const int s = m & 127, ch = (m >> 7) & 31, h = (m >> 12) & 15, b = m >> 16;
                    const size_t oidx = (((size_t)b * T_) + ch * CS_ + s) * C_ + h * D_ + n;
                    C[oidx] = v;
                } else {
                    C[(size_t)m * N + n] = v;
                }
            }
        }
    }
}

// ---------------- per-chunk cumsum + chunk sums ----------------
__global__ void chunk_scan_kernel(const float* __restrict__ gm,
                                  float* __restrict__ lcm,
                                  float* __restrict__ csum)
{
    const int blk = blockIdx.x;
    const int d   = threadIdx.x;
    const int ch  = blk % NC_;
    const int h   = (blk / NC_) % H_;
    const int b   = blk / (NC_ * H_);
    const float* src = gm + (((size_t)b * T_) + ch * CS_) * C_ + h * D_ + d;
    float* dst = lcm + (size_t)blk * CS_ * D_ + d;
    float acc = 0.f;
    for (int s = 0; s < CS_; s++) {
        acc += src[(size_t)s * C_];
        dst[(size_t)s * D_] = acc;
    }
    csum[(size_t)blk * D_ + d] = acc;
}

// ---------------- cross-chunk exclusive scan + carry LayerNorm ----------------
__global__ void carry_ln_kernel(const float* __restrict__ csum,
                                const float* __restrict__ g,
                                const float* __restrict__ bb,
                                float* __restrict__ ncar)
{
    const int bh = blockIdx.x;
    const int d  = threadIdx.x;
    const int lane = d & 31, w = d >> 5;
    __shared__ float sh[2];
    const float gd = g[d], bd = bb[d];
    float run = 0.f;
    for (int ch = 0; ch < NC_; ch++) {
        const float carry = run;
        run += csum[(size_t)(bh * NC_ + ch) * D_ + d];
        float s = warpSum(carry);
        if (lane == 0) sh[w] = s;
        __syncthreads();
        const float mean = (sh[0] + sh[1]) * (1.f / 64.f);
        __syncthreads();
        const float df = carry - mean;
        float s2 = warpSum(df * df);
        if (lane == 0) sh[w] = s2;
        __syncthreads();
        const float var = (sh[0] + sh[1]) * (1.f / 64.f);
        __syncthreads();
        ncar[(size_t)(bh * NC_ + ch) * D_ + d] = df * rsqrtf(var + EPS_) * gd + bd;
    }
}

// ---------------- cards (LN over D) + comb = [x_h | cards] ----------------
__global__ __launch_bounds__(128)
void cards_comb_kernel(const float* __restrict__ x,
                       const float* __restrict__ lcm,
                       const float* __restrict__ ncar,
                       const float* __restrict__ cg,
                       const float* __restrict__ cb,
                       float* __restrict__ comb)
{
    const int blk = blockIdx.x;
    const int s   = threadIdx.x;
    const int ch  = blk % NC_;
    const int h   = (blk / NC_) % H_;
    const int b   = blk / (NC_ * H_);

    __shared__ float ncs[D_], gs[D_], bs[D_];
    if (s < D_) { ncs[s] = ncar[(size_t)blk * D_ + s]; gs[s] = cg[s]; bs[s] = cb[s]; }
    __syncthreads();

    float v[D_];
    if (s == 0) {
#pragma unroll
        for (int d = 0; d < D_; d++) v[d] = ncs[d];
    } else {
        const float4* l4 = reinterpret_cast<const float4*>(
            lcm + ((size_t)blk * CS_ + (s - 1)) * D_);
#pragma unroll
        for (int i = 0; i < D_ / 4; i++) {
            const float4 t = l4[i];
            v[4 * i + 0] = t.x + ncs[4 * i + 0];
            v[4 * i + 1] = t.y + ncs[4 * i + 1];
            v[4 * i + 2] = t.z + ncs[4 * i + 2];
            v[4 * i + 3] = t.w + ncs[4 * i + 3];
        }
    }
    float sum = 0.f;
#pragma unroll
    for (int d = 0; d < D_; d++) sum += v[d];
    const float mean = sum * (1.f / 64.f);
    float sq = 0.f;
#pragma unroll
    for (int d = 0; d < D_; d++) { const float df = v[d] - mean; sq += df * df; }
    const float rs = rsqrtf(sq * (1.f / 64.f) + EPS_);

    const size_t row = (size_t)blk * CS_ + s;
    float4* cout = reinterpret_cast<float4*>(comb + row * 128);
    const float4* xr = reinterpret_cast<const float4*>(
        x + (((size_t)b * T_) + ch * CS_ + s) * C_ + h * D_);
#pragma unroll
    for (int i = 0; i < D_ / 4; i++) cout[i] = xr[i];
#pragma unroll
    for (int i = 0; i < D_ / 4; i++) {
        float4 t;
        t.x = (v[4 * i + 0] - mean) * rs * gs[4 * i + 0] + bs[4 * i + 0];
        t.y = (v[4 * i + 1] - mean) * rs * gs[4 * i + 1] + bs[4 * i + 1];
        t.z = (v[4 * i + 2] - mean) * rs * gs[4 * i + 2] + bs[4 * i + 2];
        t.w = (v[4 * i + 3] - mean) * rs * gs[4 * i + 3] + bs[4 * i + 3];
        cout[16 + i] = t;
    }
}

// ---------------- final LayerNorm over C + residual ----------------
__global__ __launch_bounds__(256)
void ln_res_kernel(const float* __restrict__ p, const float* __restrict__ x,
                   const float* __restrict__ g, const float* __restrict__ bb,
                   float* __restrict__ out)
{
    const int row = blockIdx.x;
    const int t   = threadIdx.x;
    const float4 lv = reinterpret_cast<const float4*>(p + (size_t)row * C_)[t];
    float s = lv.x + lv.y + lv.z + lv.w;
    __shared__ float red[8];
    s = warpSum(s);
    if ((t & 31) == 0) red[t >> 5] = s;
    __syncthreads();
    float tot = 0.f;
#pragma unroll
    for (int i = 0; i < 8; i++) tot += red[i];
    const float mean = tot * (1.f / 1024.f);
    __syncthreads();
    const float d0 = lv.x - mean, d1 = lv.y - mean, d2 = lv.z - mean, d3 = lv.w - mean;
    float sq = d0 * d0 + d1 * d1 + d2 * d2 + d3 * d3;
    sq = warpSum(sq);
    if ((t & 31) == 0) red[t >> 5] = sq;
    __syncthreads();
    float v2 = 0.f;
#pragma unroll
    for (int i = 0; i < 8; i++) v2 += red[i];
    const float rs = rsqrtf(v2 * (1.f / 1024.f) + EPS_);
    const float4 xv = reinterpret_cast<const float4*>(x + (size_t)row * C_)[t];
    const float4 gv = reinterpret_cast<const float4*>(g)[t];
    const float4 bv = reinterpret_cast<const float4*>(bb)[t];
    float4 o;
    o.x = xv.x + d0 * rs * gv.x + bv.x;
    o.y = xv.y + d1 * rs * gv.y + bv.y;
    o.z = xv.z + d2 * rs * gv.z + bv.z;
    o.w = xv.w + d3 * rs * gv.w + bv.w;
    reinterpret_cast<float4*>(out + (size_t)row * C_)[t] = o;
}

// ---------------- launch ----------------
extern "C" void kernel_launch(void* const* d_in, const int* in_sizes, int n_in,
                              void* d_out, int out_size)
{
    const float* x       = (const float*)d_in[0];
    const float* mark_W  = (const float*)d_in[1];
    const float* mark_b  = (const float*)d_in[2];
    const float* gate_W  = (const float*)d_in[3];
    const float* gate_b  = (const float*)d_in[4];
    const float* carry_g = (const float*)d_in[5];
    const float* carry_b = (const float*)d_in[6];
    const float* card_g  = (const float*)d_in[7];
    const float* card_b  = (const float*)d_in[8];
    const float* ho1_W   = (const float*)d_in[9];
    const float* ho1_b   = (const float*)d_in[10];
    const float* ho2_W   = (const float*)d_in[11];
    const float* ho2_b   = (const float*)d_in[12];
    const float* proj_W  = (const float*)d_in[13];
    const float* proj_b  = (const float*)d_in[14];
    const float* ln_g    = (const float*)d_in[15];
    const float* ln_b    = (const float*)d_in[16];
    float* out = (float*)d_out;

    static float *pm = nullptr, *lcm, *csum, *ncar, *comb, *hbuf, *obuf, *pbuf;
    if (!pm) {
        cudaGetSymbolAddress((void**)&pm,   g_pm);
        cudaGetSymbolAddress((void**)&lcm,  g_lcm);
        cudaGetSymbolAddress((void**)&csum, g_csum);
        cudaGetSymbolAddress((void**)&ncar, g_ncar);
        cudaGetSymbolAddress((void**)&comb, g_comb);
        cudaGetSymbolAddress((void**)&hbuf, g_h);
        cudaGetSymbolAddress((void**)&obuf, g_obuf);
        cudaGetSymbolAddress((void**)&pbuf, g_pbuf);
    }

    const int M  = B_ * T_;              // 16384
    const int MR = B_ * H_ * NC_ * CS_;  // 262144

    // pm = x @ mark_W + mark_b
    tgemm<128, 0><<<dim3(C_ / 128, M / 128), 256>>>(M, C_, C_, x, mark_W, mark_b, pm);
    // gm = sigmoid(x @ gate_W + gate_b) * pm   (in place over pm)
    tgemm<128, 1><<<dim3(C_ / 128, M / 128), 256>>>(M, C_, C_, x, gate_W, gate_b, pm);
    // per-chunk cumsum + chunk sums
    chunk_scan_kernel<<<B_ * H_ * NC_, 64>>>(pm, lcm, csum);
    // exclusive cross-chunk scan + LN(carries)
    carry_ln_kernel<<<B_ * H_, 64>>>(csum, carry_g, carry_b, ncar);
    // cards LN + comb assembly
    cards_comb_kernel<<<B_ * H_ * NC_, 128>>>(x, lcm, ncar, card_g, card_b, comb);
    // h = gelu(comb @ ho1_W + ho1_b)
    tgemm<128, 2><<<dim3(1, MR / 128), 256>>>(MR, 128, 128, comb, ho1_W, ho1_b, hbuf);
    // ho = h @ ho2_W + ho2_b -> scattered to (b,t,c)
    tgemm<64, 3><<<dim3(1, MR / 128), 256>>>(MR, 64, 128, hbuf, ho2_W, ho2_b, obuf);
    // proj
    tgemm<128, 0><<<dim3(C_ / 128, M / 128), 256>>>(M, C_, C_, obuf, proj_W, proj_b, pbuf);
    // final LN + residual
    ln_res_kernel<<<M, 256>>>(pbuf, x, ln_g, ln_b, out);
}

// round 4
// speedup vs baseline: 2.9814x; 1.3489x over previous
#include <cuda_runtime.h>
#include <math.h>
#include <stdint.h>

#define B_   4
#define T_   4096
#define C_   1024
#define H_   16
#define CS_  128
#define D_   64
#define NC_  32
#define EPS_ 1e-5f

// ---------------- scratch (device globals; no allocations allowed) ----------------
__device__ float g_pm  [(size_t)16384 * 1024];   // pm, then gm in-place
__device__ float g_lcm [(size_t)262144 * 64];    // per-chunk cumsum
__device__ float g_csum[2048 * 64];
__device__ float g_ncar[2048 * 64];
__device__ float g_comb[(size_t)262144 * 128];   // [x_h | cards] (tf32-rounded)
__device__ float g_h   [(size_t)262144 * 128];   // gelu(comb@W1) (tf32-rounded)
__device__ float g_obuf[(size_t)16384 * 1024];   // ho scattered (tf32-rounded)
__device__ float g_pbuf[(size_t)16384 * 1024];   // proj out pre-LN
__device__ float g_xr  [(size_t)16384 * 1024];   // x tf32-rounded
__device__ float g_wmT [(size_t)1024 * 1024];    // W^T [N,K] tf32-rounded
__device__ float g_wgT [(size_t)1024 * 1024];
__device__ float g_wpT [(size_t)1024 * 1024];
__device__ float g_w1T [128 * 128];
__device__ float g_w2T [64 * 128];

__device__ __forceinline__ float warpSum(float v) {
#pragma unroll
    for (int o = 16; o > 0; o >>= 1) v += __shfl_xor_sync(0xffffffffu, v, o);
    return v;
}

__device__ __forceinline__ float tf32r(float f) {
    uint32_t u;
    asm("cvt.rna.tf32.f32 %0, %1;" : "=r"(u) : "f"(f));
    return __uint_as_float(u);
}

__device__ __forceinline__ uint32_t smem_u32(const void* p) {
    uint32_t a;
    asm("{ .reg .u64 t; cvta.to.shared.u64 t, %1; cvt.u32.u64 %0, t; }" : "=r"(a) : "l"(p));
    return a;
}
__device__ __forceinline__ void cp16(uint32_t dst, const void* src) {
    asm volatile("cp.async.cg.shared.global [%0], [%1], 16;" :: "r"(dst), "l"(src));
}
#define LDSM4(r0, r1, r2, r3, addr) \
    asm volatile("ldmatrix.sync.aligned.m8n8.x4.shared.b16 {%0,%1,%2,%3}, [%4];" \
        : "=r"(r0), "=r"(r1), "=r"(r2), "=r"(r3) : "r"(addr))

__device__ __forceinline__ void mma_tf32(float c[4],
                                         uint32_t a0, uint32_t a1, uint32_t a2, uint32_t a3,
                                         uint32_t b0, uint32_t b1) {
    asm volatile(
        "mma.sync.aligned.m16n8k8.row.col.f32.tf32.tf32.f32 "
        "{%0,%1,%2,%3}, {%4,%5,%6,%7}, {%8,%9}, {%0,%1,%2,%3};"
        : "+f"(c[0]), "+f"(c[1]), "+f"(c[2]), "+f"(c[3])
        : "r"(a0), "r"(a1), "r"(a2), "r"(a3), "r"(b0), "r"(b1));
}

// stage ROWS x 32 fp32 tile (rows of 128B) into swizzled smem via cp.async
// phys granule (16B) within a row: g ^ (row & 7)
template <int ROWS>
__device__ __forceinline__ void stage_tile(uint32_t sdst, const float* __restrict__ gsrc,
                                           int K, int tid) {
#pragma unroll
    for (int i = 0; i < ROWS / 16; i++) {
        const int c = i * 128 + tid;
        const int m = c >> 3, g4 = c & 7;
        cp16(sdst + (uint32_t)(m * 128 + ((g4 ^ (m & 7)) << 4)),
             gsrc + (size_t)m * K + g4 * 4);
    }
}

// ============================ TF32 mma.sync GEMM (ldmatrix + cp.async) ============================
// A[M,K] row-major (tf32-rounded fp32), Bt[N,K] row-major (transposed weight, tf32-rounded).
// CTA tile 128 x BN x 32, 128 threads (4 warps, 2x2 of 64 x BN/2).
// EPI: 0 = bias; 1 = sigmoid(v)*C_old in place; 2 = gelu (+tf32 round);
//      3 = bias + (b,t,c) scatter (+tf32 round)
template <int BN, int EPI>
__global__ __launch_bounds__(128)
void tgemm2(int M, int N, int K,
            const float* __restrict__ A,
            const float* __restrict__ Bt,
            const float* __restrict__ bias,
            float* __restrict__ C)
{
    constexpr int WN = BN / 2, NT2 = WN / 8, NPAIR = NT2 / 2;
    constexpr int ASZ = 128 * 128;   // bytes per A buffer
    constexpr int BSZ = BN * 128;

    extern __shared__ char smem[];
    const uint32_t sA = smem_u32(smem);
    const uint32_t sB = sA + 2 * ASZ;

    const int tid = threadIdx.x, wid = tid >> 5, lane = tid & 31;
    const int wy = wid >> 1, wx = wid & 1;
    const int gid = lane >> 2, tig = lane & 3;
    const int lrow = lane & 15, lgh = lane >> 4;

    const int crow = blockIdx.y * 128, ccol = blockIdx.x * BN;
    const float* Ag = A + (size_t)crow * K;
    const float* Bg = Bt + (size_t)ccol * K;

    float acc[4][NT2][4];
#pragma unroll
    for (int q = 0; q < 4; q++)
#pragma unroll
        for (int nt = 0; nt < NT2; nt++)
#pragma unroll
            for (int e = 0; e < 4; e++) acc[q][nt][e] = 0.f;

    const int nT = K / 32;

    stage_tile<128>(sA, Ag, K, tid);
    stage_tile<BN>(sB, Bg, K, tid);
    asm volatile("cp.async.commit_group;");

    for (int t = 0; t < nT; t++) {
        const int buf = t & 1;
        if (t + 1 < nT) {
            const int k0 = (t + 1) * 32;
            stage_tile<128>(sA + (buf ^ 1) * ASZ, Ag + k0, K, tid);
            stage_tile<BN>(sB + (buf ^ 1) * BSZ, Bg + k0, K, tid);
            asm volatile("cp.async.commit_group;");
            asm volatile("cp.async.wait_group 1;" ::: "memory");
        } else {
            asm volatile("cp.async.wait_group 0;" ::: "memory");
        }
        __syncthreads();

        const uint32_t aBase = sA + buf * ASZ;
        const uint32_t bBase = sB + buf * BSZ;
#pragma unroll
        for (int kk2 = 0; kk2 < 8; kk2 += 2) {      // k8 step: granules kk2, kk2+1
            uint32_t a[4][4];
#pragma unroll
            for (int q = 0; q < 4; q++) {
                const int row = wy * 64 + q * 16 + lrow;
                const uint32_t ad = aBase + row * 128 + (((kk2 + lgh) ^ (row & 7)) << 4);
                LDSM4(a[q][0], a[q][1], a[q][2], a[q][3], ad);
            }
            uint32_t bfr[NT2][2];
#pragma unroll
            for (int p = 0; p < NPAIR; p++) {
                const int row = wx * WN + p * 16 + lrow;
                const uint32_t ad = bBase + row * 128 + (((kk2 + lgh) ^ (row & 7)) << 4);
                uint32_t r0, r1, r2, r3;
                LDSM4(r0, r1, r2, r3, ad);
                bfr[2 * p][0] = r0; bfr[2 * p + 1][0] = r1;
                bfr[2 * p][1] = r2; bfr[2 * p + 1][1] = r3;
            }
#pragma unroll
            for (int q = 0; q < 4; q++)
#pragma unroll
                for (int nt = 0; nt < NT2; nt++)
                    mma_tf32(acc[q][nt], a[q][0], a[q][1], a[q][2], a[q][3],
                             bfr[nt][0], bfr[nt][1]);
        }
        __syncthreads();
    }

    // epilogue
#pragma unroll
    for (int q = 0; q < 4; q++) {
#pragma unroll
        for (int nt = 0; nt < NT2; nt++) {
#pragma unroll
            for (int eh = 0; eh < 2; eh++) {
                const int m = crow + wy * 64 + q * 16 + gid + eh * 8;
                const int n = ccol + wx * WN + nt * 8 + tig * 2;
                float2 v;
                v.x = acc[q][nt][eh * 2 + 0] + bias[n];
                v.y = acc[q][nt][eh * 2 + 1] + bias[n + 1];
                if (EPI == 1) {
                    float2* p = reinterpret_cast<float2*>(C + (size_t)m * N + n);
                    const float2 old = *p;
                    v.x = old.x / (1.f + __expf(-v.x));
                    v.y = old.y / (1.f + __expf(-v.y));
                    *p = v;
                } else if (EPI == 2) {
                    v.x = tf32r(0.5f * v.x * (1.f + erff(v.x * 0.70710678118654752440f)));
                    v.y = tf32r(0.5f * v.y * (1.f + erff(v.y * 0.70710678118654752440f)));
                    *reinterpret_cast<float2*>(C + (size_t)m * N + n) = v;
                } else if (EPI == 3) {
                    const int s = m & 127, ch = (m >> 7) & 31, h = (m >> 12) & 15, b = m >> 16;
                    const size_t oidx = (((size_t)b * T_) + ch * CS_ + s) * C_ + h * D_ + n;
                    v.x = tf32r(v.x);
                    v.y = tf32r(v.y);
                    *reinterpret_cast<float2*>(C + oidx) = v;
                } else {
                    *reinterpret_cast<float2*>(C + (size_t)m * N + n) = v;
                }
            }
        }
    }
}

// ============================ converts ============================
__global__ __launch_bounds__(256)
void cvt_round_kernel(const float4* __restrict__ src, float4* __restrict__ dst, int n4)
{
    const int i = blockIdx.x * blockDim.x + threadIdx.x;
    if (i >= n4) return;
    float4 v = src[i];
    v.x = tf32r(v.x); v.y = tf32r(v.y); v.z = tf32r(v.z); v.w = tf32r(v.w);
    dst[i] = v;
}

// W [Kd,Nd] -> Wt [Nd,Kd], tf32-rounded. block (32,8), grid (Nd/32, Kd/32)
__global__ void cvt_wt_kernel(const float* __restrict__ W, float* __restrict__ Wt,
                              int Kd, int Nd)
{
    __shared__ float tile[32][33];
    const int k0 = blockIdx.y * 32, n0 = blockIdx.x * 32;
    const int tx = threadIdx.x, ty = threadIdx.y;
#pragma unroll
    for (int j = 0; j < 32; j += 8)
        tile[ty + j][tx] = W[(size_t)(k0 + ty + j) * Nd + n0 + tx];
    __syncthreads();
#pragma unroll
    for (int j = 0; j < 32; j += 8)
        Wt[(size_t)(n0 + ty + j) * Kd + k0 + tx] = tf32r(tile[tx][ty + j]);
}

// ---------------- per-chunk cumsum + chunk sums ----------------
__global__ void chunk_scan_kernel(const float* __restrict__ gm,
                                  float* __restrict__ lcm,
                                  float* __restrict__ csum)
{
    const int blk = blockIdx.x;
    const int d   = threadIdx.x;
    const int ch  = blk % NC_;
    const int h   = (blk / NC_) % H_;
    const int b   = blk / (NC_ * H_);
    const float* src = gm + (((size_t)b * T_) + ch * CS_) * C_ + h * D_ + d;
    float* dst = lcm + (size_t)blk * CS_ * D_ + d;
    float acc = 0.f;
    for (int s = 0; s < CS_; s++) {
        acc += src[(size_t)s * C_];
        dst[(size_t)s * D_] = acc;
    }
    csum[(size_t)blk * D_ + d] = acc;
}

// ---------------- cross-chunk exclusive scan + carry LayerNorm ----------------
__global__ void carry_ln_kernel(const float* __restrict__ csum,
                                const float* __restrict__ g,
                                const float* __restrict__ bb,
                                float* __restrict__ ncar)
{
    const int bh = blockIdx.x;
    const int d  = threadIdx.x;
    const int lane = d & 31, w = d >> 5;
    __shared__ float sh[2];
    const float gd = g[d], bd = bb[d];
    float run = 0.f;
    for (int ch = 0; ch < NC_; ch++) {
        const float carry = run;
        run += csum[(size_t)(bh * NC_ + ch) * D_ + d];
        float s = warpSum(carry);
        if (lane == 0) sh[w] = s;
        __syncthreads();
        const float mean = (sh[0] + sh[1]) * (1.f / 64.f);
        __syncthreads();
        const float df = carry - mean;
        float s2 = warpSum(df * df);
        if (lane == 0) sh[w] = s2;
        __syncthreads();
        const float var = (sh[0] + sh[1]) * (1.f / 64.f);
        __syncthreads();
        ncar[(size_t)(bh * NC_ + ch) * D_ + d] = df * rsqrtf(var + EPS_) * gd + bd;
    }
}

// ---------------- cards (LN over D) + comb = [x_h | cards], tf32-rounded ----------------
__global__ __launch_bounds__(128)
void cards_comb_kernel(const float* __restrict__ x,
                       const float* __restrict__ lcm,
                       const float* __restrict__ ncar,
                       const float* __restrict__ cg,
                       const float* __restrict__ cb,
                       float* __restrict__ comb)
{
    const int blk = blockIdx.x;
    const int s   = threadIdx.x;
    const int ch  = blk % NC_;
    const int h   = (blk / NC_) % H_;
    const int b   = blk / (NC_ * H_);

    __shared__ float ncs[D_], gs[D_], bs[D_];
    if (s < D_) { ncs[s] = ncar[(size_t)blk * D_ + s]; gs[s] = cg[s]; bs[s] = cb[s]; }
    __syncthreads();

    float v[D_];
    if (s == 0) {
#pragma unroll
        for (int d = 0; d < D_; d++) v[d] = ncs[d];
    } else {
        const float4* l4 = reinterpret_cast<const float4*>(
            lcm + ((size_t)blk * CS_ + (s - 1)) * D_);
#pragma unroll
        for (int i = 0; i < D_ / 4; i++) {
            const float4 t = l4[i];
            v[4 * i + 0] = t.x + ncs[4 * i + 0];
            v[4 * i + 1] = t.y + ncs[4 * i + 1];
            v[4 * i + 2] = t.z + ncs[4 * i + 2];
            v[4 * i + 3] = t.w + ncs[4 * i + 3];
        }
    }
    float sum = 0.f;
#pragma unroll
    for (int d = 0; d < D_; d++) sum += v[d];
    const float mean = sum * (1.f / 64.f);
    float sq = 0.f;
#pragma unroll
    for (int d = 0; d < D_; d++) { const float df = v[d] - mean; sq += df * df; }
    const float rs = rsqrtf(sq * (1.f / 64.f) + EPS_);

    const size_t row = (size_t)blk * CS_ + s;
    float4* cout = reinterpret_cast<float4*>(comb + row * 128);
    const float4* xr = reinterpret_cast<const float4*>(
        x + (((size_t)b * T_) + ch * CS_ + s) * C_ + h * D_);
#pragma unroll
    for (int i = 0; i < D_ / 4; i++) {
        float4 t = xr[i];
        t.x = tf32r(t.x); t.y = tf32r(t.y); t.z = tf32r(t.z); t.w = tf32r(t.w);
        cout[i] = t;
    }
#pragma unroll
    for (int i = 0; i < D_ / 4; i++) {
        float4 t;
        t.x = tf32r((v[4 * i + 0] - mean) * rs * gs[4 * i + 0] + bs[4 * i + 0]);
        t.y = tf32r((v[4 * i + 1] - mean) * rs * gs[4 * i + 1] + bs[4 * i + 1]);
        t.z = tf32r((v[4 * i + 2] - mean) * rs * gs[4 * i + 2] + bs[4 * i + 2]);
        t.w = tf32r((v[4 * i + 3] - mean) * rs * gs[4 * i + 3] + bs[4 * i + 3]);
        cout[16 + i] = t;
    }
}

// ---------------- final LayerNorm over C + residual ----------------
__global__ __launch_bounds__(256)
void ln_res_kernel(const float* __restrict__ p, const float* __restrict__ x,
                   const float* __restrict__ g, const float* __restrict__ bb,
                   float* __restrict__ out)
{
    const int row = blockIdx.x;
    const int t   = threadIdx.x;
    const float4 lv = reinterpret_cast<const float4*>(p + (size_t)row * C_)[t];
    float s = lv.x + lv.y + lv.z + lv.w;
    __shared__ float red[8];
    s = warpSum(s);
    if ((t & 31) == 0) red[t >> 5] = s;
    __syncthreads();
    float tot = 0.f;
#pragma unroll
    for (int i = 0; i < 8; i++) tot += red[i];
    const float mean = tot * (1.f / 1024.f);
    __syncthreads();
    const float d0 = lv.x - mean, d1 = lv.y - mean, d2 = lv.z - mean, d3 = lv.w - mean;
    float sq = d0 * d0 + d1 * d1 + d2 * d2 + d3 * d3;
    sq = warpSum(sq);
    if ((t & 31) == 0) red[t >> 5] = sq;
    __syncthreads();
    float v2 = 0.f;
#pragma unroll
    for (int i = 0; i < 8; i++) v2 += red[i];
    const float rs = rsqrtf(v2 * (1.f / 1024.f) + EPS_);
    const float4 xv = reinterpret_cast<const float4*>(x + (size_t)row * C_)[t];
    const float4 gv = reinterpret_cast<const float4*>(g)[t];
    const float4 bv = reinterpret_cast<const float4*>(bb)[t];
    float4 o;
    o.x = xv.x + d0 * rs * gv.x + bv.x;
    o.y = xv.y + d1 * rs * gv.y + bv.y;
    o.z = xv.z + d2 * rs * gv.z + bv.z;
    o.w = xv.w + d3 * rs * gv.w + bv.w;
    reinterpret_cast<float4*>(out + (size_t)row * C_)[t] = o;
}

// ---------------- launch ----------------
extern "C" void kernel_launch(void* const* d_in, const int* in_sizes, int n_in,
                              void* d_out, int out_size)
{
    const float* x       = (const float*)d_in[0];
    const float* mark_W  = (const float*)d_in[1];
    const float* mark_b  = (const float*)d_in[2];
    const float* gate_W  = (const float*)d_in[3];
    const float* gate_b  = (const float*)d_in[4];
    const float* carry_g = (const float*)d_in[5];
    const float* carry_b = (const float*)d_in[6];
    const float* card_g  = (const float*)d_in[7];
    const float* card_b  = (const float*)d_in[8];
    const float* ho1_W   = (const float*)d_in[9];
    const float* ho1_b   = (const float*)d_in[10];
    const float* ho2_W   = (const float*)d_in[11];
    const float* ho2_b   = (const float*)d_in[12];
    const float* proj_W  = (const float*)d_in[13];
    const float* proj_b  = (const float*)d_in[14];
    const float* ln_g    = (const float*)d_in[15];
    const float* ln_b    = (const float*)d_in[16];
    float* out = (float*)d_out;

    static float *pm = nullptr, *lcm, *csum, *ncar, *comb, *hbuf, *obuf, *pbuf;
    static float *xr, *wmT, *wgT, *wpT, *w1T, *w2T;
    if (!pm) {
        cudaGetSymbolAddress((void**)&pm,   g_pm);
        cudaGetSymbolAddress((void**)&lcm,  g_lcm);
        cudaGetSymbolAddress((void**)&csum, g_csum);
        cudaGetSymbolAddress((void**)&ncar, g_ncar);
        cudaGetSymbolAddress((void**)&comb, g_comb);
        cudaGetSymbolAddress((void**)&hbuf, g_h);
        cudaGetSymbolAddress((void**)&obuf, g_obuf);
        cudaGetSymbolAddress((void**)&pbuf, g_pbuf);
        cudaGetSymbolAddress((void**)&xr,   g_xr);
        cudaGetSymbolAddress((void**)&wmT,  g_wmT);
        cudaGetSymbolAddress((void**)&wgT,  g_wgT);
        cudaGetSymbolAddress((void**)&wpT,  g_wpT);
        cudaGetSymbolAddress((void**)&w1T,  g_w1T);
        cudaGetSymbolAddress((void**)&w2T,  g_w2T);
        const int S128 = 2 * (16384 + 16384);   // 64 KB
        const int S64  = 2 * (16384 + 8192);    // 48 KB
        cudaFuncSetAttribute(tgemm2<128, 0>, cudaFuncAttributeMaxDynamicSharedMemorySize, S128);
        cudaFuncSetAttribute(tgemm2<128, 1>, cudaFuncAttributeMaxDynamicSharedMemorySize, S128);
        cudaFuncSetAttribute(tgemm2<128, 2>, cudaFuncAttributeMaxDynamicSharedMemorySize, S128);
        cudaFuncSetAttribute(tgemm2<64, 3>,  cudaFuncAttributeMaxDynamicSharedMemorySize, S64);
    }

    const int M  = B_ * T_;              // 16384
    const int MR = B_ * H_ * NC_ * CS_;  // 262144
    const int n4 = M * C_ / 4;
    const int S128 = 2 * (16384 + 16384);
    const int S64  = 2 * (16384 + 8192);

    // pre-round / transpose
    cvt_round_kernel<<<(n4 + 255) / 256, 256>>>((const float4*)x, (float4*)xr, n4);
    cvt_wt_kernel<<<dim3(32, 32), dim3(32, 8)>>>(mark_W, wmT, 1024, 1024);
    cvt_wt_kernel<<<dim3(32, 32), dim3(32, 8)>>>(gate_W, wgT, 1024, 1024);
    cvt_wt_kernel<<<dim3(32, 32), dim3(32, 8)>>>(proj_W, wpT, 1024, 1024);
    cvt_wt_kernel<<<dim3(4, 4),   dim3(32, 8)>>>(ho1_W,  w1T, 128, 128);
    cvt_wt_kernel<<<dim3(2, 4),   dim3(32, 8)>>>(ho2_W,  w2T, 128, 64);

    // pm = x @ mark_W + mark_b
    tgemm2<128, 0><<<dim3(8, 128), 128, S128>>>(M, C_, C_, xr, wmT, mark_b, pm);
    // gm = sigmoid(x @ gate_W + gate_b) * pm   (in place)
    tgemm2<128, 1><<<dim3(8, 128), 128, S128>>>(M, C_, C_, xr, wgT, gate_b, pm);

    chunk_scan_kernel<<<B_ * H_ * NC_, 64>>>(pm, lcm, csum);
    carry_ln_kernel<<<B_ * H_, 64>>>(csum, carry_g, carry_b, ncar);
    cards_comb_kernel<<<B_ * H_ * NC_, 128>>>(x, lcm, ncar, card_g, card_b, comb);

    // h = gelu(comb @ ho1_W + ho1_b)
    tgemm2<128, 2><<<dim3(1, MR / 128), 128, S128>>>(MR, 128, 128, comb, w1T, ho1_b, hbuf);
    // ho = h @ ho2_W + ho2_b -> scattered to (b,t,c)
    tgemm2<64, 3><<<dim3(1, MR / 128), 128, S64>>>(MR, 64, 128, hbuf, w2T, ho2_b, obuf);

    // proj
    tgemm2<128, 0><<<dim3(8, 128), 128, S128>>>(M, C_, C_, obuf, wpT, proj_b, pbuf);

    ln_res_kernel<<<M, 256>>>(pbuf, x, ln_g, ln_b, out);
}